// round 13
// baseline (speedup 1.0000x reference)
#include <cuda_runtime.h>
#include <cuda_bf16.h>

// SurvLoss, single fused persistent kernel.
// log(cumsum(exp)) is monotone => segment_max = value at LAST occurrence index.
//
// R13: 512 blocks x 32768-elem tiles, launch_bounds(256,4) => 64-reg budget
//      (R12's occupancy-8/32-reg config starved MLP: DRAM stuck at 42%).
//      592 resident slots >= 512 keeps the grid barrier deadlock-free.
//
// Phase A: stream 192MB; warp w of block b owns contiguous elems
//          [b*32768 + w*4096, +4096); register exp-sum doubles as span sum.
//          smem last-occurrence filter+atomicMax, count histogram; flush.
// Barrier: last arriver scans 512 block sums (double, exclusive), releases
//          via atomicExch; others poll with volatile loads.
// Phase B: block-per-segment (b and b+512): partial = span sums before
//          region + <=4096-elem recompute (L2-hot tail tiles).
// Final:   done-counter; last block writes scalar + resets state.

#define NUM_TIMES 1024
#define NBLK      512
#define THREADS   256
#define ITERS     32
#define TILE      32768

__device__ float              g_wsum[NBLK * 8];   // per-warp 4096-elem exp sums
__device__ float              g_block_agg[NBLK];
__device__ double             g_block_prefix[NBLK];
__device__ int                g_last[NUM_TIMES];  // 0 = empty, else idx+1
__device__ int                g_cnt[NUM_TIMES];
__device__ double             g_s1;
__device__ unsigned long long g_obs;
__device__ double             g_s2;
__device__ unsigned int       g_arrive;
__device__ unsigned int       g_done2;
__device__ __align__(128) volatile unsigned int g_release[32];

__global__ void __launch_bounds__(THREADS, 4)
fused_main(const float* __restrict__ outs,
           const int* __restrict__ T_E,
           const int* __restrict__ T_T,
           float* __restrict__ out) {
    __shared__ int   s_last[NUM_TIMES];
    __shared__ int   s_cnt[NUM_TIMES];
    __shared__ float wtot[8];
    __shared__ float rs1[8];
    __shared__ int   rob[8];
    __shared__ int   s_flag;
    __shared__ int   sh_e[2], sh_cnt[2];

    const int b = blockIdx.x, tid = threadIdx.x;
    const int lane = tid & 31, w = tid >> 5;

    for (int i = tid; i < NUM_TIMES; i += THREADS) { s_last[i] = 0; s_cnt[i] = 0; }
    __syncthreads();

    const float4* o4 = (const float4*)outs;
    const int4*   e4 = (const int4*)T_E;
    const int4*   t4 = (const int4*)T_T;
    // warp w owns contiguous float4s [b*8192 + w*1024, +1024)
    const int wbase = b * (TILE / 4) + w * 1024;

    float thr_tot = 0.f;
    float ls1 = 0.f;
    int   lob = 0;

    // ---- Phase A: streaming (reverse order: filter kills most atomicMax) ----
#pragma unroll 8
    for (int c = ITERS - 1; c >= 0; --c) {
        const int fi = wbase + c * 32 + lane;
        float4 v  = o4[fi];
        int4   tt = t4[fi];
        int4   te = e4[fi];

        thr_tot += __expf(v.x) + __expf(v.y) + __expf(v.z) + __expf(v.w);

        const int gi = fi * 4;
        // T_T in [0, NUM_TIMES) by construction
        int sg0 = tt.x, sg1 = tt.y, sg2 = tt.z, sg3 = tt.w;

        if (s_last[sg3] < gi + 4) atomicMax(&s_last[sg3], gi + 4);
        if (s_last[sg2] < gi + 3) atomicMax(&s_last[sg2], gi + 3);
        if (s_last[sg1] < gi + 2) atomicMax(&s_last[sg1], gi + 2);
        if (s_last[sg0] < gi + 1) atomicMax(&s_last[sg0], gi + 1);

        if (te.x) atomicAdd(&s_cnt[sg0], 1);
        if (te.y) atomicAdd(&s_cnt[sg1], 1);
        if (te.z) atomicAdd(&s_cnt[sg2], 1);
        if (te.w) atomicAdd(&s_cnt[sg3], 1);

        ls1 += te.x ? v.x : 0.f;
        ls1 += te.y ? v.y : 0.f;
        ls1 += te.z ? v.z : 0.f;
        ls1 += te.w ? v.w : 0.f;
        lob += te.x + te.y + te.z + te.w;
    }

    // warp reduce: exp region sum (contiguous span), s1, obs
    float xx = thr_tot;
#pragma unroll
    for (int o = 16; o; o >>= 1) {
        xx  += __shfl_xor_sync(0xffffffffu, xx, o);
        ls1 += __shfl_xor_sync(0xffffffffu, ls1, o);
        lob += __shfl_xor_sync(0xffffffffu, lob, o);
    }
    if (lane == 0) {
        g_wsum[b * 8 + w] = xx;
        wtot[w] = xx; rs1[w] = ls1; rob[w] = lob;
    }
    __syncthreads();
    if (tid == 0) {
        float bt = 0.f, bs = 0.f; int bo = 0;
#pragma unroll
        for (int k = 0; k < 8; k++) { bt += wtot[k]; bs += rs1[k]; bo += rob[k]; }
        g_block_agg[b] = bt;
        atomicAdd(&g_s1, (double)bs);
        atomicAdd(&g_obs, (unsigned long long)bo);
    }

    // flush segment tables to global
    __syncthreads();
    for (int i = tid; i < NUM_TIMES; i += THREADS) {
        int m = s_last[i];
        if (m) atomicMax(&g_last[i], m);
        int cnt = s_cnt[i];
        if (cnt) atomicAdd(&g_cnt[i], cnt);
    }

    // ---- grid barrier (all 512 blocks resident: 4/SM * 148 = 592) ----
    __threadfence();
    __syncthreads();
    if (tid == 0) s_flag = (atomicAdd(&g_arrive, 1u) == NBLK - 1u);
    __syncthreads();
    if (s_flag) {
        // last arriver: exclusive double scan of the 512 block sums
        double v0 = (double)__ldcg(&g_block_agg[2 * tid + 0]);
        double v1 = (double)__ldcg(&g_block_agg[2 * tid + 1]);
        double c0 = v0, c1 = c0 + v1;

        double x = c1;
#pragma unroll
        for (int o = 1; o < 32; o <<= 1) {
            double y = __shfl_up_sync(0xffffffffu, x, o);
            if (lane >= o) x += y;
        }
        __shared__ double wsc[8];
        if (lane == 31) wsc[w] = x;
        __syncthreads();
        double wexcl = 0.0;
#pragma unroll
        for (int k = 0; k < 8; k++) if (k < w) wexcl += wsc[k];
        double excl = wexcl + (x - c1);

        g_block_prefix[2 * tid + 0] = excl;
        g_block_prefix[2 * tid + 1] = excl + c0;
        __syncthreads();
        if (tid == 0) {
            __threadfence();
            atomicExch((unsigned int*)&g_release[0], 1u);
        }
    } else {
        if (tid == 0) {
            int backoff = 32;
            while (g_release[0] == 0u) {        // volatile L2 reads, no atomic convoy
                __nanosleep(backoff);
                if (backoff < 1024) backoff <<= 1;
            }
        }
        __syncthreads();
    }
    __threadfence();

    // ---- Phase B: block b handles segments b and b+512 ----
#pragma unroll 1
    for (int round = 0; round < 2; round++) {
        const int t = b + round * NBLK;
        if (tid == 0) {
            sh_e[round]   = __ldcg(&g_last[t]);
            sh_cnt[round] = __ldcg(&g_cnt[t]);
            g_last[t] = 0;      // sole reader -> reset for next replay
            g_cnt[t]  = 0;
        }
        __syncthreads();
        const int e = sh_e[round], cnt = sh_cnt[round];

        if (e > 0 && cnt > 0) {
            const int idx = e - 1;
            const int bo  = idx >> 15;           // owning tile
            const int wr  = (idx >> 12) & 7;     // warp-region within tile
            const int r   = idx & 4095;          // last included elem in region
            const int ql  = r >> 2;              // last float4 (0..1023)
            const int rem = r & 3;

            float acc = 0.f;
            if (tid < wr) acc = g_wsum[bo * 8 + tid];   // full regions before

            const float4* o4b = (const float4*)outs + bo * (TILE / 4) + wr * 1024;
#pragma unroll
            for (int k = 0; k < 4; k++) {
                const int q = tid + k * THREADS;
                if (q <= ql) {
                    float4 v = o4b[q];
                    float s = __expf(v.x);
                    if (q < ql) {
                        s += __expf(v.y) + __expf(v.z) + __expf(v.w);
                    } else {
                        if (rem >= 1) s += __expf(v.y);
                        if (rem >= 2) s += __expf(v.z);
                        if (rem >= 3) s += __expf(v.w);
                    }
                    acc += s;
                }
            }
#pragma unroll
            for (int o = 16; o; o >>= 1) acc += __shfl_xor_sync(0xffffffffu, acc, o);
            if (lane == 0) wtot[w] = acc;        // reuse as scratch
            __syncthreads();
            if (tid == 0) {
                float pt = 0.f;
#pragma unroll
                for (int kk = 0; kk < 8; kk++) pt += wtot[kk];
                double total = g_block_prefix[bo] + (double)pt;
                double y = log(total);
                if (y < 0.0) y = 0.0;
                atomicAdd(&g_s2, y * (double)cnt);
            }
            __syncthreads();
        }
    }

    // ---- finalize ----
    __threadfence();
    __syncthreads();
    if (tid == 0) {
        if (atomicAdd(&g_done2, 1u) == NBLK - 1u) {
            double s2t = atomicAdd(&g_s2, 0.0);
            double s1t = atomicAdd(&g_s1, 0.0);
            unsigned long long obs = atomicAdd(&g_obs, 0ull);
            out[0] = (float)((s2t - s1t) / (double)obs);
            g_s2 = 0.0; g_s1 = 0.0; g_obs = 0ull;
            g_arrive = 0u; g_done2 = 0u;
            atomicExch((unsigned int*)&g_release[0], 0u);
        }
    }
}

// ---------------------------------------------------------------- launch
extern "C" void kernel_launch(void* const* d_in, const int* in_sizes, int n_in,
                              void* d_out, int out_size) {
    const float* outs = (const float*)d_in[0];
    const int*   T_E  = (const int*)d_in[1];
    const int*   T_T  = (const int*)d_in[2];
    float* out = (float*)d_out;

    fused_main<<<NBLK, THREADS>>>(outs, T_E, T_T, out);
}